// round 8
// baseline (speedup 1.0000x reference)
#include <cuda_runtime.h>
#include <cuda_bf16.h>
#include <cstdint>

#define BB 4
#define NN 8192
#define NPOINT 2048
#define CC 64
#define NS 32
#define NSP 33      // NSAMPLE + 1 (fps_idx prepended)
#define TOTCH 70    // 3 + 3 + 64
#define NC1 10      // grid cells per axis (cell size = radius = 0.1)
#define NCELLS 1000
#define BUFSZ 128   // per-ball candidate cap (expected ~34 hits)

// Scratch (device globals — no allocations allowed)
__device__ float4 g_p4[BB * NN];        // xyz by original index (w unused)
__device__ int    g_off[BB * NCELLS];   // cell start
__device__ int    g_end[BB * NCELLS];   // cell end
__device__ float4 g_g4[BB * NN];        // cell-sorted (x,y,z, idx-bits)
__device__ float4 g_ft4[BB * NN * (CC / 4)];  // features (B,N,C) as float4

// ---------------------------------------------------------------------------
__device__ __forceinline__ int cell_coord(float v) {
    int c = (int)(v * 10.0f);
    return c < 0 ? 0 : (c > 9 ? 9 : c);
}

// Kernel 1: transpose features (B,C,N) -> (B,N,C). Each block: 32c x 64n
// (two 32x32 tiles) to raise per-block ILP; float4 on both sides.
__global__ void feat_transpose_kernel(const float* __restrict__ f) {
    __shared__ float tile[2][32][33];
    const int n0 = blockIdx.x * 64;
    const int c0 = blockIdx.y * 32;
    const int b  = blockIdx.z;
    const int t  = threadIdx.x;

    #pragma unroll
    for (int h = 0; h < 2; h++) {
        const int c = t >> 3, n4 = t & 7;
        const float4 v = *(const float4*)
            &f[((size_t)(b * CC + c0 + c)) * NN + n0 + h * 32 + n4 * 4];
        float* tw = &tile[h][c][n4 * 4];
        tw[0] = v.x; tw[1] = v.y; tw[2] = v.z; tw[3] = v.w;
    }
    __syncthreads();
    #pragma unroll
    for (int h = 0; h < 2; h++) {
        const int n = t >> 3, c4 = t & 7;
        float4 v;
        v.x = tile[h][c4 * 4 + 0][n];
        v.y = tile[h][c4 * 4 + 1][n];
        v.z = tile[h][c4 * 4 + 2][n];
        v.w = tile[h][c4 * 4 + 3][n];
        *(float4*)((float*)g_ft4 +
                   ((size_t)(b * NN + n0 + h * 32 + n)) * CC + c0 + c4 * 4) = v;
    }
}

// Kernel 2: fused prep + grid build — one block per batch.
__global__ __launch_bounds__(1024) void grid_build_kernel(
        const float* __restrict__ xyz) {
    __shared__ unsigned short cell16[NN];
    __shared__ int hist[NCELLS];
    __shared__ int wsum[32];
    const int b = blockIdx.x;
    const int t = threadIdx.x;
    const int lane = t & 31;
    const int wid = t >> 5;

    if (t < NCELLS) hist[t] = 0;
    __syncthreads();

    for (int p = t; p < NN; p += 1024) {
        const float x = xyz[(b * NN + p) * 3 + 0];
        const float y = xyz[(b * NN + p) * 3 + 1];
        const float z = xyz[(b * NN + p) * 3 + 2];
        g_p4[b * NN + p] = make_float4(x, y, z, 0.0f);
        const int cell =
            (cell_coord(z) * NC1 + cell_coord(y)) * NC1 + cell_coord(x);
        cell16[p] = (unsigned short)cell;
        atomicAdd(&hist[cell], 1);
    }
    __syncthreads();

    const int orig = (t < NCELLS) ? hist[t] : 0;
    int v = orig;
    #pragma unroll
    for (int d = 1; d < 32; d <<= 1) {
        const int n = __shfl_up_sync(0xffffffffu, v, d);
        if (lane >= d) v += n;
    }
    if (lane == 31) wsum[wid] = v;
    __syncthreads();
    if (wid == 0) {
        int s = wsum[lane];
        #pragma unroll
        for (int d = 1; d < 32; d <<= 1) {
            const int n = __shfl_up_sync(0xffffffffu, s, d);
            if (lane >= d) s += n;
        }
        wsum[lane] = s;
    }
    __syncthreads();
    const int excl = v - orig + (wid > 0 ? wsum[wid - 1] : 0);
    if (t < NCELLS) {
        g_off[b * NCELLS + t] = excl;
        g_end[b * NCELLS + t] = excl + orig;
    }
    __syncthreads();
    if (t < NCELLS) hist[t] = excl;
    __syncthreads();

    for (int p = t; p < NN; p += 1024) {
        const int cell = cell16[p];
        const int pos = atomicAdd(&hist[cell], 1);
        float4 q = g_p4[b * NN + p];
        q.w = __int_as_float(p);
        g_g4[b * NN + pos] = q;
    }
}

// ---------------------------------------------------------------------------
// Kernel 3: fused ball-query + gather. Block = 4 warps = 4 ADJACENT balls.
// Phase B: 2 passes x 32 channels — each staging LDG.128 covers a FULL 128B
// feature line (wavefront floor). Output rows (132 floats per channel per
// block) written as float4.
// ---------------------------------------------------------------------------
#define FW 4
#define PCH 32                       // channels per pass
#define TROW 132                     // 4 balls * 33 slots

__global__ __launch_bounds__(FW * 32, 11) void bq_gather_kernel(
        const float* __restrict__ new_xyz,
        const int* __restrict__ fps_idx,
        float* __restrict__ out) {
    __shared__ float s_tile[PCH * TROW];   // [ch][132]; head aliased as buf
    __shared__ float s_cxs[3][TROW];       // centered xyz rows
    __shared__ int   s_sidx[FW][NSP];

    const int tid  = threadIdx.x;
    const int lane = tid & 31;
    const int wid  = tid >> 5;
    const int w = blockIdx.x * FW + wid;
    const int b = w / NPOINT;
    const int j0 = (blockIdx.x * FW) % NPOINT;

    const float cx = __ldg(&new_xyz[w * 3 + 0]);
    const float cy = __ldg(&new_xyz[w * 3 + 1]);
    const float cz = __ldg(&new_xyz[w * 3 + 2]);
    const float r2 = __fmul_rn(0.1f, 0.1f);

    // per-warp candidate buffer aliases the tile (disjoint phases)
    unsigned short* buf = (unsigned short*)s_tile + wid * BUFSZ;

    // ---- Phase A: collection ----
    const int icx = cell_coord(cx), icy = cell_coord(cy), icz = cell_coord(cz);
    const int x0 = icx > 0 ? icx - 1 : 0, x1 = icx < 9 ? icx + 1 : 9;
    const int y0 = icy > 0 ? icy - 1 : 0, y1 = icy < 9 ? icy + 1 : 9;
    const int z0 = icz > 0 ? icz - 1 : 0, z1 = icz < 9 ? icz + 1 : 9;
    const int ny = y1 - y0 + 1;
    const int nrows = (z1 - z0 + 1) * ny;

    // lane-parallel prefetch of the <=9 row ranges, broadcast via shfl
    int mys = 0, mye = 0;
    if (lane < nrows) {
        const int zz = z0 + lane / ny;
        const int yy = y0 + lane % ny;
        const int rowbase = b * NCELLS + (zz * NC1 + yy) * NC1;
        mys = g_off[rowbase + x0];
        mye = g_end[rowbase + x1];
    }

    const unsigned below = (1u << lane) - 1u;
    int cnt = 0;

    for (int r = 0; r < nrows; r++) {
        const int start = __shfl_sync(0xffffffffu, mys, r);
        const int end   = __shfl_sync(0xffffffffu, mye, r);
        for (int k = start; k < end; k += 32) {
            const int kk = k + lane;
            bool valid = false;
            int pi = 0;
            if (kk < end) {
                const float4 p = g_g4[b * NN + kk];
                const float dx = __fsub_rn(cx, p.x);
                const float dy = __fsub_rn(cy, p.y);
                const float dz = __fsub_rn(cz, p.z);
                const float d2 = __fadd_rn(
                    __fadd_rn(__fmul_rn(dx, dx), __fmul_rn(dy, dy)),
                    __fmul_rn(dz, dz));
                valid = d2 < r2;
                pi = __float_as_int(p.w);
            }
            const unsigned m = __ballot_sync(0xffffffffu, valid);
            if (valid) {
                const int pos = cnt + __popc(m & below);
                if (pos < BUFSZ) buf[pos] = (unsigned short)pi;
            }
            cnt += __popc(m);
        }
    }
    if (cnt > BUFSZ) cnt = BUFSZ;
    __syncwarp();

    // rank-select smallest NS into sidx[1..NS] (== scan-order semantics)
    int vmin = 0x7fffffff;
    for (int t = lane; t < cnt; t += 32) {
        const int v = buf[t];
        int rank = 0;
        for (int k = 0; k < cnt; k++) rank += (buf[k] < v);
        if (rank < NS) s_sidx[wid][1 + rank] = v;
        if (v < vmin) vmin = v;
    }
    #pragma unroll
    for (int d = 16; d > 0; d >>= 1) {
        const int o = __shfl_xor_sync(0xffffffffu, vmin, d);
        if (o < vmin) vmin = o;
    }
    const int pad = (cnt > 0) ? vmin : 0;
    if (lane < NS && lane >= cnt) s_sidx[wid][1 + lane] = pad;
    if (lane == 0) s_sidx[wid][0] = fps_idx[w];
    __syncwarp();

    // centered xyz rows (lane = s; lane 0 also s = 32). Conflict-free STS.
    {
        const int i = s_sidx[wid][lane];
        const float4 p = g_p4[b * NN + i];
        s_cxs[0][wid * 33 + lane] = __fsub_rn(p.x, cx);
        s_cxs[1][wid * 33 + lane] = __fsub_rn(p.y, cy);
        s_cxs[2][wid * 33 + lane] = __fsub_rn(p.z, cz);
        if (lane == 0) {
            const int i32 = s_sidx[wid][32];
            const float4 q = g_p4[b * NN + i32];
            s_cxs[0][wid * 33 + 32] = __fsub_rn(q.x, cx);
            s_cxs[1][wid * 33 + 32] = __fsub_rn(q.y, cy);
            s_cxs[2][wid * 33 + 32] = __fsub_rn(q.z, cz);
        }
    }
    __syncthreads();

    // ---- Phase B ----
    const size_t chstr = (size_t)NPOINT * NSP;
    float* __restrict__ outb0 =
        out + ((size_t)b * TOTCH * NPOINT + j0) * NSP;

    // xyz channels 0..5: 6 x 33 float4 = 198 vectorized stores
    for (int e = tid; e < 6 * 33; e += FW * 32) {
        const int ch = (e * 993) >> 15;        // e / 33
        const int q  = e - ch * 33;
        const int k3 = (ch < 3) ? ch : ch - 3;
        const float4 v = *(const float4*)&s_cxs[k3][q * 4];
        *(float4*)(outb0 + (size_t)ch * chstr + q * 4) = v;
    }

    // features: 2 passes x 32 channels
    const int c4 = lane & 7;        // float4 id within pass (8 x 4 = 32 ch)
    const int ls = lane >> 3;       // 4 s values per staging iter
    #pragma unroll
    for (int p = 0; p < 2; p++) {
        // staging: per s, lanes c4=0..7 cover the full 128B line
        const float4* __restrict__ ftb =
            g_ft4 + (size_t)(b * NN) * 16 + p * 8 + c4;
        #pragma unroll
        for (int s0 = 0; s0 < NSP; s0 += 4) {
            const int s = s0 + ls;
            if (s < NSP) {
                const int i = s_sidx[wid][s];
                const float4 v = ftb[(size_t)i * 16];
                float* tw = &s_tile[(c4 * 4) * TROW + wid * 33 + s];
                tw[0 * TROW] = v.x; tw[1 * TROW] = v.y;
                tw[2 * TROW] = v.z; tw[3 * TROW] = v.w;
            }
        }
        __syncthreads();

        // writes: 32 ch * 33 float4 = 1056 vectorized stores
        for (int e = tid; e < PCH * 33; e += FW * 32) {
            const int ch = (e * 993) >> 15;    // e / 33
            const int q  = e - ch * 33;
            const float4 v = *(const float4*)&s_tile[ch * TROW + q * 4];
            *(float4*)(outb0 + (size_t)(6 + p * PCH + ch) * chstr + q * 4) = v;
        }
        __syncthreads();
    }
}

// ---------------------------------------------------------------------------
extern "C" void kernel_launch(void* const* d_in, const int* in_sizes, int n_in,
                              void* d_out, int out_size) {
    const float* xyz      = (const float*)d_in[0];   // (B, N, 3)
    const float* new_xyz  = (const float*)d_in[1];   // (B, NPOINT, 3)
    const float* features = (const float*)d_in[2];   // (B, C, N)
    const int*   fps_idx  = (const int*)d_in[3];     // (B, NPOINT)
    float* out = (float*)d_out;

    {
        dim3 grid(NN / 64, CC / 32, BB);
        feat_transpose_kernel<<<grid, 256>>>(features);
    }
    grid_build_kernel<<<BB, 1024>>>(xyz);
    {
        const int blocks = (BB * NPOINT) / FW;   // 2048
        bq_gather_kernel<<<blocks, FW * 32>>>(new_xyz, fps_idx, out);
    }
}

// round 10
// speedup vs baseline: 1.1859x; 1.1859x over previous
#include <cuda_runtime.h>
#include <cuda_bf16.h>
#include <cstdint>

#define BB 4
#define NN 8192
#define NPOINT 2048
#define CC 64
#define NS 32
#define NSP 33      // NSAMPLE + 1 (fps_idx prepended)
#define TOTCH 70    // 3 + 3 + 64
#define NC1 10      // grid cells per axis (cell size = radius = 0.1)
#define NCELLS 1000
#define BUFSZ 128   // per-ball candidate cap (expected ~34 hits)

// Scratch (device globals — no allocations allowed)
__device__ float4 g_p4[BB * NN];        // xyz by original index (w unused)
__device__ int    g_off[BB * NCELLS];   // cell start
__device__ int    g_end[BB * NCELLS];   // cell end
__device__ float4 g_g4[BB * NN];        // cell-sorted (x,y,z, idx-bits)
__device__ float4 g_ft4[BB * NN * (CC / 4)];  // features (B,N,C) as float4

// ---------------------------------------------------------------------------
__device__ __forceinline__ int cell_coord(float v) {
    int c = (int)(v * 10.0f);
    return c < 0 ? 0 : (c > 9 ? 9 : c);
}

// ---------------------------------------------------------------------------
// Kernel 1 (fused preprocessing): blocks 0..3 build the spatial grid (one
// block per batch); blocks 4..515 transpose features (B,C,N)->(B,N,C).
// The two jobs touch disjoint buffers and overlap on the chip, hiding the
// 4-block grid build behind the transpose.
// ---------------------------------------------------------------------------
#define GB_BLOCKS BB                         // 4
#define FT_BLOCKS (BB * (CC / 32) * (NN / 128))   // 4*2*64 = 512

__global__ __launch_bounds__(1024) void pre_kernel(
        const float* __restrict__ f,
        const float* __restrict__ xyz) {
    __shared__ union {
        float tile[4][32][33];                           // transpose: 16.9KB
        struct {                                         // grid build: 20.2KB
            unsigned short cell16[NN];
            int hist[NCELLS];
            int wsum[32];
        } gb;
    } sm;

    const int t = threadIdx.x;

    if (blockIdx.x < GB_BLOCKS) {
        // ================= grid build (one block per batch) =================
        const int b = blockIdx.x;
        const int lane = t & 31;
        const int wid = t >> 5;

        if (t < NCELLS) sm.gb.hist[t] = 0;
        __syncthreads();

        for (int p = t; p < NN; p += 1024) {
            const float x = xyz[(b * NN + p) * 3 + 0];
            const float y = xyz[(b * NN + p) * 3 + 1];
            const float z = xyz[(b * NN + p) * 3 + 2];
            g_p4[b * NN + p] = make_float4(x, y, z, 0.0f);
            const int cell =
                (cell_coord(z) * NC1 + cell_coord(y)) * NC1 + cell_coord(x);
            sm.gb.cell16[p] = (unsigned short)cell;
            atomicAdd(&sm.gb.hist[cell], 1);
        }
        __syncthreads();

        const int orig = (t < NCELLS) ? sm.gb.hist[t] : 0;
        int v = orig;
        #pragma unroll
        for (int d = 1; d < 32; d <<= 1) {
            const int n = __shfl_up_sync(0xffffffffu, v, d);
            if (lane >= d) v += n;
        }
        if (lane == 31) sm.gb.wsum[wid] = v;
        __syncthreads();
        if (wid == 0) {
            int s = sm.gb.wsum[lane];
            #pragma unroll
            for (int d = 1; d < 32; d <<= 1) {
                const int n = __shfl_up_sync(0xffffffffu, s, d);
                if (lane >= d) s += n;
            }
            sm.gb.wsum[lane] = s;
        }
        __syncthreads();
        const int excl = v - orig + (wid > 0 ? sm.gb.wsum[wid - 1] : 0);
        if (t < NCELLS) {
            g_off[b * NCELLS + t] = excl;
            g_end[b * NCELLS + t] = excl + orig;
        }
        __syncthreads();
        if (t < NCELLS) sm.gb.hist[t] = excl;    // scatter cursors
        __syncthreads();

        for (int p = t; p < NN; p += 1024) {
            const int cell = sm.gb.cell16[p];
            const int pos = atomicAdd(&sm.gb.hist[cell], 1);
            float4 q = g_p4[b * NN + p];
            q.w = __int_as_float(p);
            g_g4[b * NN + pos] = q;
        }
    } else {
        // ================= feature transpose =================
        const int bid2 = blockIdx.x - GB_BLOCKS;
        const int b    = bid2 >> 7;            // / 128
        const int r    = bid2 & 127;
        const int c0   = (r >> 6) * 32;        // cblk in {0,1}
        const int n0   = (r & 63) * 128;       // nblk in 0..63

        const int h  = t >> 8;                 // 0..3 (sub-tile)
        const int tt = t & 255;

        {
            const int c = tt >> 3, q = tt & 7;
            const float4 v = *(const float4*)
                &f[((size_t)(b * CC + c0 + c)) * NN + n0 + h * 32 + q * 4];
            float* tw = &sm.tile[h][c][q * 4];
            tw[0] = v.x; tw[1] = v.y; tw[2] = v.z; tw[3] = v.w;
        }
        __syncthreads();
        {
            const int n = tt >> 3, c4 = tt & 7;
            float4 v;
            v.x = sm.tile[h][c4 * 4 + 0][n];
            v.y = sm.tile[h][c4 * 4 + 1][n];
            v.z = sm.tile[h][c4 * 4 + 2][n];
            v.w = sm.tile[h][c4 * 4 + 3][n];
            *(float4*)((float*)g_ft4 +
                ((size_t)(b * NN + n0 + h * 32 + n)) * CC + c0 + c4 * 4) = v;
        }
    }
}

// ---------------------------------------------------------------------------
// Kernel 2: fused ball-query + gather (identical to the best-measured R7
// version). Block = 4 warps = 4 ADJACENT balls; smem ~10.6KB -> 16 blocks/SM.
// ---------------------------------------------------------------------------
#define FW 4
#define PCH 16                       // channels per pass
#define TROW 132                     // 4 balls * 33 slots

__global__ __launch_bounds__(FW * 32, 16) void bq_gather_kernel(
        const float* __restrict__ new_xyz,
        const int* __restrict__ fps_idx,
        float* __restrict__ out) {
    __shared__ float s_tile[PCH * TROW];   // [ch][132]; head aliased as buf
    __shared__ int   s_sidx[FW][NSP];
    __shared__ float s_cxs[FW][3][NSP];

    const int tid  = threadIdx.x;
    const int lane = tid & 31;
    const int wid  = tid >> 5;
    const int w = blockIdx.x * FW + wid;
    const int b = w / NPOINT;
    const int j0 = (blockIdx.x * FW) % NPOINT;

    const float cx = __ldg(&new_xyz[w * 3 + 0]);
    const float cy = __ldg(&new_xyz[w * 3 + 1]);
    const float cz = __ldg(&new_xyz[w * 3 + 2]);
    const float r2 = __fmul_rn(0.1f, 0.1f);

    unsigned short* buf = (unsigned short*)s_tile + wid * BUFSZ;

    // ---- Phase A: collection ----
    const int icx = cell_coord(cx), icy = cell_coord(cy), icz = cell_coord(cz);
    const int x0 = icx > 0 ? icx - 1 : 0, x1 = icx < 9 ? icx + 1 : 9;
    const int y0 = icy > 0 ? icy - 1 : 0, y1 = icy < 9 ? icy + 1 : 9;
    const int z0 = icz > 0 ? icz - 1 : 0, z1 = icz < 9 ? icz + 1 : 9;
    const int ny = y1 - y0 + 1;
    const int nrows = (z1 - z0 + 1) * ny;

    int mys = 0, mye = 0;
    if (lane < nrows) {
        const int zz = z0 + lane / ny;
        const int yy = y0 + lane % ny;
        const int rowbase = b * NCELLS + (zz * NC1 + yy) * NC1;
        mys = g_off[rowbase + x0];
        mye = g_end[rowbase + x1];
    }

    const unsigned below = (1u << lane) - 1u;
    int cnt = 0;

    for (int r = 0; r < nrows; r++) {
        const int start = __shfl_sync(0xffffffffu, mys, r);
        const int end   = __shfl_sync(0xffffffffu, mye, r);
        for (int k = start; k < end; k += 32) {
            const int kk = k + lane;
            bool valid = false;
            int pi = 0;
            if (kk < end) {
                const float4 p = g_g4[b * NN + kk];
                const float dx = __fsub_rn(cx, p.x);
                const float dy = __fsub_rn(cy, p.y);
                const float dz = __fsub_rn(cz, p.z);
                const float d2 = __fadd_rn(
                    __fadd_rn(__fmul_rn(dx, dx), __fmul_rn(dy, dy)),
                    __fmul_rn(dz, dz));
                valid = d2 < r2;
                pi = __float_as_int(p.w);
            }
            const unsigned m = __ballot_sync(0xffffffffu, valid);
            if (valid) {
                const int pos = cnt + __popc(m & below);
                if (pos < BUFSZ) buf[pos] = (unsigned short)pi;
            }
            cnt += __popc(m);
        }
    }
    if (cnt > BUFSZ) cnt = BUFSZ;
    __syncwarp();

    // rank-select smallest NS into sidx[1..NS] (== scan-order semantics)
    int vmin = 0x7fffffff;
    for (int t = lane; t < cnt; t += 32) {
        const int v = buf[t];
        int rank = 0;
        for (int k = 0; k < cnt; k++) rank += (buf[k] < v);
        if (rank < NS) s_sidx[wid][1 + rank] = v;
        if (v < vmin) vmin = v;
    }
    #pragma unroll
    for (int d = 16; d > 0; d >>= 1) {
        const int o = __shfl_xor_sync(0xffffffffu, vmin, d);
        if (o < vmin) vmin = o;
    }
    const int pad = (cnt > 0) ? vmin : 0;
    if (lane < NS && lane >= cnt) s_sidx[wid][1 + lane] = pad;
    if (lane == 0) s_sidx[wid][0] = fps_idx[w];
    __syncwarp();

    // centered xyz into smem
    {
        const int i = s_sidx[wid][lane];
        const float4 p = g_p4[b * NN + i];
        s_cxs[wid][0][lane] = __fsub_rn(p.x, cx);
        s_cxs[wid][1][lane] = __fsub_rn(p.y, cy);
        s_cxs[wid][2][lane] = __fsub_rn(p.z, cz);
        if (lane == 0) {
            const int i32 = s_sidx[wid][32];
            const float4 q = g_p4[b * NN + i32];
            s_cxs[wid][0][32] = __fsub_rn(q.x, cx);
            s_cxs[wid][1][32] = __fsub_rn(q.y, cy);
            s_cxs[wid][2][32] = __fsub_rn(q.z, cz);
        }
    }
    __syncthreads();

    // ---- Phase B ----
    const size_t chstr = (size_t)NPOINT * NSP;
    float* __restrict__ outb0 =
        out + ((size_t)b * TOTCH * NPOINT + j0) * NSP;

    #pragma unroll
    for (int k = 0; k < 6; k++) {
        const int k3 = (k < 3) ? k : k - 3;
        float* __restrict__ dst = outb0 + (size_t)k * chstr;
        {
            const int w4 = (tid * 993) >> 15;     // tid / 33
            const int s  = tid - w4 * 33;
            dst[tid] = s_cxs[w4][k3][s];
        }
        if (tid < 4) dst[128 + tid] = s_cxs[3][k3][29 + tid];
    }

    const int c4 = lane & 3;        // float4 id within pass (4 channels)
    const int ls = lane >> 2;       // 8 s values per staging iter
    #pragma unroll
    for (int p = 0; p < 4; p++) {
        const float4* __restrict__ ftb =
            g_ft4 + (size_t)(b * NN) * 16 + p * 4 + c4;
        #pragma unroll
        for (int s0 = 0; s0 < 32; s0 += 8) {
            const int s = s0 + ls;
            const int i = s_sidx[wid][s];
            const float4 v = ftb[(size_t)i * 16];
            float* tw = &s_tile[(c4 * 4) * TROW + wid * 33 + s];
            tw[0 * TROW] = v.x; tw[1 * TROW] = v.y;
            tw[2 * TROW] = v.z; tw[3 * TROW] = v.w;
        }
        if (lane < 4) {   // s = 32
            const int i = s_sidx[wid][32];
            const float4 v = ftb[(size_t)i * 16];   // c4 = lane
            float* tw = &s_tile[(lane * 4) * TROW + wid * 33 + 32];
            tw[0 * TROW] = v.x; tw[1 * TROW] = v.y;
            tw[2 * TROW] = v.z; tw[3 * TROW] = v.w;
        }
        __syncthreads();

        for (int e = tid; e < PCH * 33; e += FW * 32) {
            const int ch = (e * 993) >> 15;        // e / 33
            const int q  = e - ch * 33;
            const float4 v = *(const float4*)&s_tile[ch * TROW + q * 4];
            *(float4*)(outb0 + (size_t)(6 + p * PCH + ch) * chstr + q * 4) = v;
        }
        __syncthreads();
    }
}

// ---------------------------------------------------------------------------
extern "C" void kernel_launch(void* const* d_in, const int* in_sizes, int n_in,
                              void* d_out, int out_size) {
    const float* xyz      = (const float*)d_in[0];   // (B, N, 3)
    const float* new_xyz  = (const float*)d_in[1];   // (B, NPOINT, 3)
    const float* features = (const float*)d_in[2];   // (B, C, N)
    const int*   fps_idx  = (const int*)d_in[3];     // (B, NPOINT)
    float* out = (float*)d_out;

    pre_kernel<<<GB_BLOCKS + FT_BLOCKS, 1024>>>(features, xyz);
    {
        const int blocks = (BB * NPOINT) / FW;   // 2048
        bq_gather_kernel<<<blocks, FW * 32>>>(new_xyz, fps_idx, out);
    }
}